// round 10
// baseline (speedup 1.0000x reference)
#include <cuda_runtime.h>
#include <cuda_fp16.h>
#include <cstdint>

#define D_IN 64
#define D_E 64
#define D_OUT 128
#define D_APPLY_IN 192
#define MAX_NODES 50000
#define MAX_EDGES 800000

__device__ float g_hneigh[MAX_NODES * D_OUT];
// packed fp16 split rows: per row 128B hi + 128B lo (64 elems each)
__device__ __align__(16) unsigned char g_nconv[(size_t)MAX_NODES * 256];
__device__ __align__(16) unsigned char g_econv[(size_t)MAX_EDGES * 256];

// ============================ helpers ============================
__device__ __forceinline__ void ffma2(unsigned long long& acc,
                                      unsigned long long a, unsigned long long b) {
    asm("fma.rn.f32x2 %0, %1, %2, %0;" : "+l"(acc) : "l"(a), "l"(b));
}
__device__ __forceinline__ float2 unpack2(unsigned long long v) {
    float2 f;
    asm("mov.b64 {%0, %1}, %2;" : "=f"(f.x), "=f"(f.y) : "l"(v));
    return f;
}
__device__ __forceinline__ void red_add_v4(float* p, float a, float b, float c, float d) {
    asm volatile("red.global.add.v4.f32 [%0], {%1, %2, %3, %4};"
                 :: "l"(p), "f"(a), "f"(b), "f"(c), "f"(d) : "memory");
}
__device__ __forceinline__ uint32_t smem_u32(const void* p) {
    uint32_t a;
    asm("{ .reg .u64 t; cvta.to.shared.u64 t, %1; cvt.u32.u64 %0, t; }" : "=r"(a) : "l"(p));
    return a;
}
__device__ __forceinline__ void ldsm4(uint32_t* r, uint32_t addr) {
    asm volatile("ldmatrix.sync.aligned.m8n8.x4.shared.b16 {%0,%1,%2,%3}, [%4];"
                 : "=r"(r[0]), "=r"(r[1]), "=r"(r[2]), "=r"(r[3]) : "r"(addr));
}
__device__ __forceinline__ void mma_f16(float* c, const uint32_t* a, uint32_t b0, uint32_t b1) {
    asm volatile("mma.sync.aligned.m16n8k16.row.col.f32.f16.f16.f32 "
                 "{%0,%1,%2,%3}, {%4,%5,%6,%7}, {%8,%9}, {%0,%1,%2,%3};"
                 : "+f"(c[0]), "+f"(c[1]), "+f"(c[2]), "+f"(c[3])
                 : "r"(a[0]), "r"(a[1]), "r"(a[2]), "r"(a[3]), "r"(b0), "r"(b1));
}
__device__ __forceinline__ void cpa16(uint32_t dst, const void* src) {
    asm volatile("cp.async.cg.shared.global [%0], [%1], 16;" :: "r"(dst), "l"(src));
}
#define CP_COMMIT() asm volatile("cp.async.commit_group;" ::: "memory")
#define CP_WAIT0()  asm volatile("cp.async.wait_group 0;" ::: "memory")
__device__ __forceinline__ void sts_zero16(uint32_t dst) {
    asm volatile("st.shared.v4.b32 [%0], {%1,%1,%1,%1};" :: "r"(dst), "r"(0u));
}

__global__ void zero_hneigh_kernel(int n4) {
    int i = blockIdx.x * blockDim.x + threadIdx.x;
    if (i < n4)
        reinterpret_cast<float4*>(g_hneigh)[i] = make_float4(0.f, 0.f, 0.f, 0.f);
}

// ---------- prepass: fp32 rows -> packed fp16 hi/lo rows (256B/row) ----------
__global__ void conv_split_kernel(const float4* __restrict__ in,
                                  unsigned char* __restrict__ out, int nchunks) {
    int i = blockIdx.x * blockDim.x + threadIdx.x;
    if (i >= nchunks) return;
    int row = i >> 4, q = i & 15;
    float4 v = in[i];
    __half2 h01 = __floats2half2_rn(v.x, v.y);
    __half2 h23 = __floats2half2_rn(v.z, v.w);
    float rx = v.x - __half2float(__low2half(h01));
    float ry = v.y - __half2float(__high2half(h01));
    float rz = v.z - __half2float(__low2half(h23));
    float rw = v.w - __half2float(__high2half(h23));
    __half2 l01 = __floats2half2_rn(rx, ry);
    __half2 l23 = __floats2half2_rn(rz, rw);
    unsigned char* o = out + (size_t)row * 256;
    *reinterpret_cast<__half2*>(o + q * 8)           = h01;
    *reinterpret_cast<__half2*>(o + q * 8 + 4)       = h23;
    *reinterpret_cast<__half2*>(o + 128 + q * 8)     = l01;
    *reinterpret_cast<__half2*>(o + 128 + q * 8 + 4) = l23;
}

// =====================================================================
// Edge kernel v8: fp16 hi/lo K-concat single GEMM (K=256).
// 512 threads, 256-edge tiles, warp grid 4(m) x 4(n), warp tile m64 x n32.
// smem: W'' 64KB (Wh duplicated along K) + X 128KB + bias.
// =====================================================================
#define SM_W    0u
#define SM_X    65536u
#define SM_BIAS 196608u
#define SM_EDGE_BYTES 197120u

// byte offset inside a (rows x 256)-fp16 tile: 512B rows, 16B-chunk XOR swizzle
__device__ __forceinline__ uint32_t toff(int row, int kchunk) {
    return ((uint32_t)row << 9) + ((uint32_t)(kchunk ^ (row & 7)) << 4);
}

__global__ __launch_bounds__(512, 1)
void edge_msg_kernel(const float* __restrict__ Wmsg,
                     const float* __restrict__ bmsg,
                     const int* __restrict__ src,
                     const int* __restrict__ dst,
                     int E)
{
    extern __shared__ char smem[];
    const uint32_t sb = smem_u32(smem);
    const int tid  = threadIdx.x;
    const int lane = tid & 31;
    const int wid  = tid >> 5;

    // ---- W'' to smem: W''[n][k] = fp16(Wmsg[k&127][n]), k = 0..255, swizzled ----
    for (int i = tid; i < 128 * 256; i += 512) {
        int n = i >> 8, k = i & 255;
        __half wh = __float2half_rn(Wmsg[(k & 127) * 128 + n]);
        uint32_t off = toff(n, k >> 3) + (k & 7) * 2;
        *reinterpret_cast<__half*>(smem + SM_W + off) = wh;
    }
    if (tid < 128) reinterpret_cast<float*>(smem + SM_BIAS)[tid] = bmsg[tid];
    __syncthreads();

    // ---- gather constants: warp handles 16 rows, 2 threads/row ----
    const int g_r    = lane >> 1;           // row within warp's 16
    const int g_h    = lane & 1;            // 0 = hi chunks (0-15), 1 = lo (16-31)
    const int g_row  = (wid << 4) + g_r;    // tile row 0..255

    // ---- warp tiling for MMA: 4(m) x 4(n), warp tile m64 x n32 ----
    const int mbase = (wid & 3) * 64;
    const int nbase = (wid >> 2) * 32;
    const int mrel  = lane & 15;
    const int khA   = lane >> 4;
    const int nrel  = (lane & 7) + ((lane >> 4) << 3);
    const int khB   = (lane >> 3) & 1;
    const uint32_t swzA = (uint32_t)(mrel & 7);
    const uint32_t swzB = (uint32_t)(nrel & 7);
    uint32_t aRow[4], bRow[2];
    #pragma unroll
    for (int mt = 0; mt < 4; ++mt) aRow[mt] = (uint32_t)(mbase + mt * 16 + mrel) << 9;
    #pragma unroll
    for (int g = 0; g < 2; ++g) bRow[g] = (uint32_t)(nbase + g * 16 + nrel) << 9;

    // bias pairs: c = nbase + nt*8 + (lane&3)*2
    float bx[4], by[4];
    {
        const float* bsm = reinterpret_cast<const float*>(smem + SM_BIAS);
        #pragma unroll
        for (int nt = 0; nt < 4; ++nt) {
            float2 bb = *reinterpret_cast<const float2*>(bsm + nbase + nt * 8 + (lane & 3) * 2);
            bx[nt] = bb.x; by[nt] = bb.y;
        }
    }

    float acc[4][4][4];
    #pragma unroll
    for (int mt = 0; mt < 4; ++mt)
        #pragma unroll
        for (int nt = 0; nt < 4; ++nt)
            #pragma unroll
            for (int q = 0; q < 4; ++q) acc[mt][nt][q] = 0.f;

    const uint32_t xS = sb + SM_X, wS = sb + SM_W;

    const int tiles = (E + 255) >> 8;
    const int grid  = gridDim.x;

    // ---- gather one 256-edge tile (convergent); 16 cpa16/thread ----
    auto issue_tile = [&](int base) {
        int sv = 0;
        {
            int ee = base + (wid << 4) + lane;
            if (lane < 16 && ee < E) sv = src[ee];
        }
        const int s  = __shfl_sync(0xffffffffu, sv, g_r);   // all lanes participate
        const int eg = base + g_row;
        const bool valid = (eg < E);
        const unsigned char* nrow = g_nconv + (size_t)s * 256 + g_h * 128;
        const unsigned char* erow = g_econv + (size_t)eg * 256 + g_h * 128;
        #pragma unroll
        for (int c = 0; c < 16; ++c) {
            const int kchunk = (g_h << 4) + c;   // 0..31
            const uint32_t d = xS + toff(g_row, kchunk);
            const unsigned char* sp = (c < 8) ? (nrow + c * 16) : (erow + (c - 8) * 16);
            if (valid) cpa16(d, sp);
            else       sts_zero16(d);
        }
    };

    // ---- persistent pipeline: wait -> sync -> MMA -> sync -> issue(t+1) -> epilogue ----
    int t = blockIdx.x;
    if (t < tiles) issue_tile(t << 8);
    CP_COMMIT();

    for (; t < tiles; t += grid) {
        CP_WAIT0();
        __syncthreads();   // stage visible from all threads

        const int base = t << 8;

        // ---- single GEMM: K=256 (16 k16-chunks) ----
        #pragma unroll
        for (int kc = 0; kc < 16; ++kc) {
            const uint32_t ka = (uint32_t)(((kc << 1) | khA) ^ swzA) << 4;
            const uint32_t kb = (uint32_t)(((kc << 1) | khB) ^ swzB) << 4;
            uint32_t afr[4][4], bfr[2][4];
            #pragma unroll
            for (int mt = 0; mt < 4; ++mt) ldsm4(afr[mt], xS + aRow[mt] + ka);
            #pragma unroll
            for (int g = 0; g < 2; ++g) ldsm4(bfr[g], wS + bRow[g] + kb);
            #pragma unroll
            for (int mt = 0; mt < 4; ++mt)
                #pragma unroll
                for (int nt = 0; nt < 4; ++nt)
                    mma_f16(acc[mt][nt], afr[mt],
                            bfr[nt >> 1][(nt & 1) * 2], bfr[nt >> 1][(nt & 1) * 2 + 1]);
        }

        __syncthreads();   // all warps finished reading the stage

        const int tn = t + grid;
        if (tn < tiles) issue_tile(tn << 8);
        CP_COMMIT();

        // ---- epilogue: bias+relu, pair-merge via shfl, red.v4 scatter ----
        #pragma unroll
        for (int mt = 0; mt < 4; ++mt) {
            const int rtop = mbase + mt * 16 + (lane >> 2);
            const int etop = base + rtop;
            const int ebot = etop + 8;
            const int dtop = (etop < E) ? dst[etop] : 0;
            const int dbot = (ebot < E) ? dst[ebot] : 0;
            const int cb   = nbase + (lane & 2) * 2;
            #pragma unroll
            for (int nt = 0; nt < 4; ++nt) {
                float v0 = fmaxf(acc[mt][nt][0] + bx[nt], 0.f);
                float v1 = fmaxf(acc[mt][nt][1] + by[nt], 0.f);
                float v2 = fmaxf(acc[mt][nt][2] + bx[nt], 0.f);
                float v3 = fmaxf(acc[mt][nt][3] + by[nt], 0.f);
                float w0 = __shfl_xor_sync(0xffffffffu, v0, 1);
                float w1 = __shfl_xor_sync(0xffffffffu, v1, 1);
                float w2 = __shfl_xor_sync(0xffffffffu, v2, 1);
                float w3 = __shfl_xor_sync(0xffffffffu, v3, 1);
                if (!(lane & 1)) {
                    if (etop < E)
                        red_add_v4(g_hneigh + (size_t)dtop * D_OUT + cb + nt * 8, v0, v1, w0, w1);
                    if (ebot < E)
                        red_add_v4(g_hneigh + (size_t)dbot * D_OUT + cb + nt * 8, v2, v3, w2, w3);
                }
                acc[mt][nt][0] = 0.f; acc[mt][nt][1] = 0.f;
                acc[mt][nt][2] = 0.f; acc[mt][nt][3] = 0.f;
            }
        }
    }
}

// =====================================================================
// Apply kernel (R3): 8 nodes/warp, f32x2 packed along k.
// =====================================================================
#define A_WT 0
#define A_BIAS 24576
#define A_X 24704
#define A_SMEM_FLOATS 37248

__global__ __launch_bounds__(256, 1)
void apply_kernel(const float* __restrict__ nfeats,
                  const float* __restrict__ Wap,
                  const float* __restrict__ bap,
                  float* __restrict__ out,
                  int N)
{
    extern __shared__ float sm[];
    float* wsm  = sm + A_WT;
    float* bsm  = sm + A_BIAS;
    float* xall = sm + A_X;

    for (int half = 0; half < 2; ++half) {
        for (int i = threadIdx.x; i < 3072; i += 256)
            reinterpret_cast<float4*>(xall)[i] =
                reinterpret_cast<const float4*>(Wap + half * 12288)[i];
        __syncthreads();
        for (int i = threadIdx.x; i < 12288; i += 256) {
            int kl = i >> 7, c = i & 127, k = half * 96 + kl;
            wsm[c * 192 + (((k >> 2) ^ ((c >> 2) & 7)) << 2) + (k & 3)] = xall[i];
        }
        __syncthreads();
    }
    if (threadIdx.x < 128) bsm[threadIdx.x] = bap[threadIdx.x];
    __syncthreads();

    const int lane = threadIdx.x & 31;
    const int warp = threadIdx.x >> 5;
    const int gw   = blockIdx.x * 8 + warp;
    const int nw   = gridDim.x * 8;
    const int s7   = lane & 7;

    float* xw = xall + warp * (8 * 196);
    const float* wl = wsm + (lane * 4) * 192;
    const float4 bias4 = *reinterpret_cast<const float4*>(bsm + lane * 4);

    const int h  = lane >> 4;
    const int j  = lane & 15;
    const int cg = j * 12;

    unsigned long long acc[8][4];
    #pragma unroll
    for (int e = 0; e < 8; ++e)
        #pragma unroll
        for (int c = 0; c < 4; ++c) acc[e][c] = 0ull;

    const int tiles = (N + 7) >> 3;
    for (int tile = gw; tile < tiles; tile += nw) {
        const int base = tile * 8;

        #pragma unroll
        for (int r = 0; r < 4; ++r) {
            int nl = r * 2 + h;
            int ng = base + nl;
            if (ng < N) {
                #pragma unroll
                for (int q = 0; q < 3; ++q) {
                    int off = cg + q * 4;
                    float4 v;
                    if (off < D_IN)
                        v = *reinterpret_cast<const float4*>(nfeats + (size_t)ng * D_IN + off);
                    else
                        v = *reinterpret_cast<const float4*>(g_hneigh + (size_t)ng * D_OUT + (off - D_IN));
                    *reinterpret_cast<float4*>(xw + nl * 196 + off) = v;
                }
            }
        }
        __syncwarp();

        #pragma unroll 4
        for (int t = 0; t < 48; ++t) {
            const int wq = ((t ^ s7) << 2);
            ulonglong2 w0 = *reinterpret_cast<const ulonglong2*>(wl + wq);
            ulonglong2 w1 = *reinterpret_cast<const ulonglong2*>(wl + 192 + wq);
            ulonglong2 w2 = *reinterpret_cast<const ulonglong2*>(wl + 384 + wq);
            ulonglong2 w3 = *reinterpret_cast<const ulonglong2*>(wl + 576 + wq);
            #pragma unroll
            for (int e = 0; e < 8; ++e) {
                ulonglong2 xv = *reinterpret_cast<const ulonglong2*>(xw + e * 196 + t * 4);
                ffma2(acc[e][0], xv.x, w0.x); ffma2(acc[e][0], xv.y, w0.y);
                ffma2(acc[e][1], xv.x, w1.x); ffma2(acc[e][1], xv.y, w1.y);
                ffma2(acc[e][2], xv.x, w2.x); ffma2(acc[e][2], xv.y, w2.y);
                ffma2(acc[e][3], xv.x, w3.x); ffma2(acc[e][3], xv.y, w3.y);
            }
        }

        #pragma unroll
        for (int e = 0; e < 8; ++e) {
            int ng = base + e;
            float2 f0 = unpack2(acc[e][0]);
            float2 f1 = unpack2(acc[e][1]);
            float2 f2 = unpack2(acc[e][2]);
            float2 f3 = unpack2(acc[e][3]);
            float4 o;
            o.x = fmaxf(f0.x + f0.y + bias4.x, 0.f);
            o.y = fmaxf(f1.x + f1.y + bias4.y, 0.f);
            o.z = fmaxf(f2.x + f2.y + bias4.z, 0.f);
            o.w = fmaxf(f3.x + f3.y + bias4.w, 0.f);
            if (ng < N)
                *reinterpret_cast<float4*>(out + (size_t)ng * D_OUT + lane * 4) = o;
            acc[e][0] = 0ull; acc[e][1] = 0ull; acc[e][2] = 0ull; acc[e][3] = 0ull;
        }
        __syncwarp();
    }
}

extern "C" void kernel_launch(void* const* d_in, const int* in_sizes, int n_in,
                              void* d_out, int out_size)
{
    const float* nfeats = (const float*)d_in[0];
    const float* efeats = (const float*)d_in[1];
    const float* Wmsg   = (const float*)d_in[2];
    const float* bmsg   = (const float*)d_in[3];
    const float* Wap    = (const float*)d_in[4];
    const float* bap    = (const float*)d_in[5];
    const int*   src    = (const int*)d_in[6];
    const int*   dst    = (const int*)d_in[7];

    const int E = in_sizes[6];
    const int N = in_sizes[0] / D_IN;

    const size_t smem_edge  = SM_EDGE_BYTES;                    // 197120 B
    const size_t smem_apply = A_SMEM_FLOATS * sizeof(float);    // 148992 B
    cudaFuncSetAttribute(edge_msg_kernel, cudaFuncAttributeMaxDynamicSharedMemorySize, (int)smem_edge);
    cudaFuncSetAttribute(apply_kernel,    cudaFuncAttributeMaxDynamicSharedMemorySize, (int)smem_apply);

    unsigned char* nconv_p; cudaGetSymbolAddress((void**)&nconv_p, g_nconv);
    unsigned char* econv_p; cudaGetSymbolAddress((void**)&econv_p, g_econv);

    // prepass conversions (fp16 hi/lo)
    {
        int nchunks = N * 16;
        conv_split_kernel<<<(nchunks + 255) / 256, 256>>>(
            (const float4*)nfeats, nconv_p, nchunks);
        int echunks = E * 16;
        conv_split_kernel<<<(echunks + 255) / 256, 256>>>(
            (const float4*)efeats, econv_p, echunks);
    }

    const int n4 = (N * D_OUT) / 4;
    zero_hneigh_kernel<<<(n4 + 255) / 256, 256>>>(n4);
    edge_msg_kernel<<<148, 512, smem_edge>>>(Wmsg, bmsg, src, dst, E);
    apply_kernel<<<152, 256, smem_apply>>>(nfeats, Wap, bap, (float*)d_out, N);
}

// round 11
// speedup vs baseline: 1.0347x; 1.0347x over previous
#include <cuda_runtime.h>
#include <cuda_fp16.h>
#include <cstdint>

#define D_IN 64
#define D_E 64
#define D_OUT 128
#define D_APPLY_IN 192
#define MAX_NODES 50000
#define MAX_EDGES 800000

__device__ float g_hneigh[MAX_NODES * D_OUT];
// packed fp16 split rows: per row 128B hi + 128B lo (64 elems each)
__device__ __align__(16) unsigned char g_nconv[(size_t)MAX_NODES * 256];
__device__ __align__(16) unsigned char g_econv[(size_t)MAX_EDGES * 256];

// ============================ helpers ============================
__device__ __forceinline__ void ffma2(unsigned long long& acc,
                                      unsigned long long a, unsigned long long b) {
    asm("fma.rn.f32x2 %0, %1, %2, %0;" : "+l"(acc) : "l"(a), "l"(b));
}
__device__ __forceinline__ float2 unpack2(unsigned long long v) {
    float2 f;
    asm("mov.b64 {%0, %1}, %2;" : "=f"(f.x), "=f"(f.y) : "l"(v));
    return f;
}
__device__ __forceinline__ void red_add_v4(float* p, float a, float b, float c, float d) {
    asm volatile("red.global.add.v4.f32 [%0], {%1, %2, %3, %4};"
                 :: "l"(p), "f"(a), "f"(b), "f"(c), "f"(d) : "memory");
}
__device__ __forceinline__ uint32_t smem_u32(const void* p) {
    uint32_t a;
    asm("{ .reg .u64 t; cvta.to.shared.u64 t, %1; cvt.u32.u64 %0, t; }" : "=r"(a) : "l"(p));
    return a;
}
__device__ __forceinline__ void ldsm4(uint32_t* r, uint32_t addr) {
    asm volatile("ldmatrix.sync.aligned.m8n8.x4.shared.b16 {%0,%1,%2,%3}, [%4];"
                 : "=r"(r[0]), "=r"(r[1]), "=r"(r[2]), "=r"(r[3]) : "r"(addr));
}
__device__ __forceinline__ void mma_f16(float* c, const uint32_t* a, uint32_t b0, uint32_t b1) {
    asm volatile("mma.sync.aligned.m16n8k16.row.col.f32.f16.f16.f32 "
                 "{%0,%1,%2,%3}, {%4,%5,%6,%7}, {%8,%9}, {%0,%1,%2,%3};"
                 : "+f"(c[0]), "+f"(c[1]), "+f"(c[2]), "+f"(c[3])
                 : "r"(a[0]), "r"(a[1]), "r"(a[2]), "r"(a[3]), "r"(b0), "r"(b1));
}
__device__ __forceinline__ void cpa16(uint32_t dst, const void* src) {
    asm volatile("cp.async.cg.shared.global [%0], [%1], 16;" :: "r"(dst), "l"(src));
}
#define CP_COMMIT() asm volatile("cp.async.commit_group;" ::: "memory")
#define CP_WAIT0()  asm volatile("cp.async.wait_group 0;" ::: "memory")
__device__ __forceinline__ void sts_zero16(uint32_t dst) {
    asm volatile("st.shared.v4.b32 [%0], {%1,%1,%1,%1};" :: "r"(dst), "r"(0u));
}

__global__ void zero_hneigh_kernel(int n4) {
    int i = blockIdx.x * blockDim.x + threadIdx.x;
    if (i < n4)
        reinterpret_cast<float4*>(g_hneigh)[i] = make_float4(0.f, 0.f, 0.f, 0.f);
}

// ---------- prepass: fp32 rows -> packed fp16 hi/lo rows (256B/row) ----------
__global__ void conv_split_kernel(const float4* __restrict__ in,
                                  unsigned char* __restrict__ out, int nchunks) {
    int i = blockIdx.x * blockDim.x + threadIdx.x;
    if (i >= nchunks) return;
    int row = i >> 4, q = i & 15;
    float4 v = in[i];
    __half2 h01 = __floats2half2_rn(v.x, v.y);
    __half2 h23 = __floats2half2_rn(v.z, v.w);
    float rx = v.x - __half2float(__low2half(h01));
    float ry = v.y - __half2float(__high2half(h01));
    float rz = v.z - __half2float(__low2half(h23));
    float rw = v.w - __half2float(__high2half(h23));
    __half2 l01 = __floats2half2_rn(rx, ry);
    __half2 l23 = __floats2half2_rn(rz, rw);
    unsigned char* o = out + (size_t)row * 256;
    *reinterpret_cast<__half2*>(o + q * 8)           = h01;
    *reinterpret_cast<__half2*>(o + q * 8 + 4)       = h23;
    *reinterpret_cast<__half2*>(o + 128 + q * 8)     = l01;
    *reinterpret_cast<__half2*>(o + 128 + q * 8 + 4) = l23;
}

// =====================================================================
// Edge kernel v9: R9 shell (2 CTAs/SM x 256 thr, 64-edge tiles) with
// fp16 hi/lo K-concat single GEMM (K=256).
// smem: W'' 64KB (Wh duplicated along K) + X 32KB + bias.
// =====================================================================
#define SM_W    0u
#define SM_X    65536u
#define SM_BIAS 98304u
#define SM_EDGE_BYTES 98816u

// byte offset inside a (rows x 256)-fp16 tile: 512B rows, 16B-chunk XOR swizzle
__device__ __forceinline__ uint32_t toff(int row, int kchunk) {
    return ((uint32_t)row << 9) + ((uint32_t)(kchunk ^ (row & 7)) << 4);
}

__global__ __launch_bounds__(256, 2)
void edge_msg_kernel(const float* __restrict__ Wmsg,
                     const float* __restrict__ bmsg,
                     const int* __restrict__ src,
                     const int* __restrict__ dst,
                     int E)
{
    extern __shared__ char smem[];
    const uint32_t sb = smem_u32(smem);
    const int tid  = threadIdx.x;
    const int lane = tid & 31;
    const int wid  = tid >> 5;

    // ---- W'' to smem: W''[n][k] = fp16(Wmsg[k&127][n]), k = 0..255, swizzled ----
    for (int i = tid; i < 128 * 256; i += 256) {
        int n = i >> 8, k = i & 255;
        __half wh = __float2half_rn(Wmsg[(k & 127) * 128 + n]);
        uint32_t off = toff(n, k >> 3) + (k & 7) * 2;
        *reinterpret_cast<__half*>(smem + SM_W + off) = wh;
    }
    if (tid < 128) reinterpret_cast<float*>(smem + SM_BIAS)[tid] = bmsg[tid];
    __syncthreads();

    // ---- gather constants: warp handles 8 rows, 4 threads/row ----
    const int g_r   = lane & 7;            // row within warp's 8
    const int g_row = (wid << 3) + g_r;    // tile row 0..63
    const int g_t   = lane >> 3;           // 0..3: (sel, h)
    const int g_sel = g_t & 1;             // 0 = node feats, 1 = edge feats
    const int g_h   = g_t >> 1;            // 0 = hi, 1 = lo

    // ---- warp tiling for MMA: 2(m) x 4(n), warp tile m32 x n32, K=256 ----
    const int mbase = (wid & 1) * 32;
    const int nbase = (wid >> 1) * 32;
    const int mrel  = lane & 15;
    const int khA   = lane >> 4;
    const int nrel  = (lane & 7) + ((lane >> 4) << 3);
    const int khB   = (lane >> 3) & 1;
    const uint32_t swzA = (uint32_t)(mrel & 7);
    const uint32_t swzB = (uint32_t)(nrel & 7);
    uint32_t aRow[2], bRow[2];
    #pragma unroll
    for (int mt = 0; mt < 2; ++mt) aRow[mt] = (uint32_t)(mbase + mt * 16 + mrel) << 9;
    #pragma unroll
    for (int g = 0; g < 2; ++g) bRow[g] = (uint32_t)(nbase + g * 16 + nrel) << 9;

    // bias pairs: c = nbase + nt*8 + (lane&3)*2
    float bx[4], by[4];
    {
        const float* bsm = reinterpret_cast<const float*>(smem + SM_BIAS);
        #pragma unroll
        for (int nt = 0; nt < 4; ++nt) {
            float2 bb = *reinterpret_cast<const float2*>(bsm + nbase + nt * 8 + (lane & 3) * 2);
            bx[nt] = bb.x; by[nt] = bb.y;
        }
    }

    float acc[2][4][4];
    #pragma unroll
    for (int mt = 0; mt < 2; ++mt)
        #pragma unroll
        for (int nt = 0; nt < 4; ++nt)
            #pragma unroll
            for (int q = 0; q < 4; ++q) acc[mt][nt][q] = 0.f;

    const uint32_t xS = sb + SM_X, wS = sb + SM_W;

    const int tiles = (E + 63) >> 6;
    const int grid  = gridDim.x;

    // ---- gather one 64-edge tile (convergent); 8 cpa16/thread ----
    auto issue_tile = [&](int base) {
        int sv = 0;
        {
            int ee = base + (wid << 3) + (lane & 7);
            if (lane < 8 && ee < E) sv = src[ee];
        }
        const int s  = __shfl_sync(0xffffffffu, sv, g_r);   // all lanes participate
        const int eg = base + g_row;
        const bool valid = (eg < E);
        const unsigned char* srow = (g_sel
            ? (g_econv + (size_t)eg * 256)
            : (g_nconv + (size_t)s * 256)) + g_h * 128;
        const int kcb = (g_h << 4) + (g_sel << 3);   // dst kchunk base
        #pragma unroll
        for (int c = 0; c < 8; ++c) {
            const uint32_t d = xS + toff(g_row, kcb + c);
            if (valid) cpa16(d, srow + c * 16);
            else       sts_zero16(d);
        }
    };

    // ---- pipeline: wait -> sync -> MMA -> sync -> issue(t+1) -> epilogue ----
    int t = blockIdx.x;
    if (t < tiles) issue_tile(t << 6);
    CP_COMMIT();

    for (; t < tiles; t += grid) {
        CP_WAIT0();
        __syncthreads();   // stage visible from all threads

        const int base = t << 6;

        // ---- single GEMM: K=256 (16 k16-chunks) ----
        #pragma unroll
        for (int kc = 0; kc < 16; ++kc) {
            const uint32_t ka = (uint32_t)(((kc << 1) | khA) ^ swzA) << 4;
            const uint32_t kb = (uint32_t)(((kc << 1) | khB) ^ swzB) << 4;
            uint32_t afr[2][4], bfr[2][4];
            #pragma unroll
            for (int mt = 0; mt < 2; ++mt) ldsm4(afr[mt], xS + aRow[mt] + ka);
            #pragma unroll
            for (int g = 0; g < 2; ++g) ldsm4(bfr[g], wS + bRow[g] + kb);
            #pragma unroll
            for (int mt = 0; mt < 2; ++mt)
                #pragma unroll
                for (int nt = 0; nt < 4; ++nt)
                    mma_f16(acc[mt][nt], afr[mt],
                            bfr[nt >> 1][(nt & 1) * 2], bfr[nt >> 1][(nt & 1) * 2 + 1]);
        }

        __syncthreads();   // all warps finished reading the stage

        const int tn = t + grid;
        if (tn < tiles) issue_tile(tn << 6);
        CP_COMMIT();

        // ---- epilogue: bias+relu, pair-merge via shfl, red.v4 scatter ----
        #pragma unroll
        for (int mt = 0; mt < 2; ++mt) {
            const int rtop = mbase + mt * 16 + (lane >> 2);
            const int etop = base + rtop;
            const int ebot = etop + 8;
            const int dtop = (etop < E) ? dst[etop] : 0;
            const int dbot = (ebot < E) ? dst[ebot] : 0;
            const int cb   = nbase + (lane & 2) * 2;
            #pragma unroll
            for (int nt = 0; nt < 4; ++nt) {
                float v0 = fmaxf(acc[mt][nt][0] + bx[nt], 0.f);
                float v1 = fmaxf(acc[mt][nt][1] + by[nt], 0.f);
                float v2 = fmaxf(acc[mt][nt][2] + bx[nt], 0.f);
                float v3 = fmaxf(acc[mt][nt][3] + by[nt], 0.f);
                float w0 = __shfl_xor_sync(0xffffffffu, v0, 1);
                float w1 = __shfl_xor_sync(0xffffffffu, v1, 1);
                float w2 = __shfl_xor_sync(0xffffffffu, v2, 1);
                float w3 = __shfl_xor_sync(0xffffffffu, v3, 1);
                if (!(lane & 1)) {
                    if (etop < E)
                        red_add_v4(g_hneigh + (size_t)dtop * D_OUT + cb + nt * 8, v0, v1, w0, w1);
                    if (ebot < E)
                        red_add_v4(g_hneigh + (size_t)dbot * D_OUT + cb + nt * 8, v2, v3, w2, w3);
                }
                acc[mt][nt][0] = 0.f; acc[mt][nt][1] = 0.f;
                acc[mt][nt][2] = 0.f; acc[mt][nt][3] = 0.f;
            }
        }
    }
}

// =====================================================================
// Apply kernel (R3): 8 nodes/warp, f32x2 packed along k.
// =====================================================================
#define A_WT 0
#define A_BIAS 24576
#define A_X 24704
#define A_SMEM_FLOATS 37248

__global__ __launch_bounds__(256, 1)
void apply_kernel(const float* __restrict__ nfeats,
                  const float* __restrict__ Wap,
                  const float* __restrict__ bap,
                  float* __restrict__ out,
                  int N)
{
    extern __shared__ float sm[];
    float* wsm  = sm + A_WT;
    float* bsm  = sm + A_BIAS;
    float* xall = sm + A_X;

    for (int half = 0; half < 2; ++half) {
        for (int i = threadIdx.x; i < 3072; i += 256)
            reinterpret_cast<float4*>(xall)[i] =
                reinterpret_cast<const float4*>(Wap + half * 12288)[i];
        __syncthreads();
        for (int i = threadIdx.x; i < 12288; i += 256) {
            int kl = i >> 7, c = i & 127, k = half * 96 + kl;
            wsm[c * 192 + (((k >> 2) ^ ((c >> 2) & 7)) << 2) + (k & 3)] = xall[i];
        }
        __syncthreads();
    }
    if (threadIdx.x < 128) bsm[threadIdx.x] = bap[threadIdx.x];
    __syncthreads();

    const int lane = threadIdx.x & 31;
    const int warp = threadIdx.x >> 5;
    const int gw   = blockIdx.x * 8 + warp;
    const int nw   = gridDim.x * 8;
    const int s7   = lane & 7;

    float* xw = xall + warp * (8 * 196);
    const float* wl = wsm + (lane * 4) * 192;
    const float4 bias4 = *reinterpret_cast<const float4*>(bsm + lane * 4);

    const int h  = lane >> 4;
    const int j  = lane & 15;
    const int cg = j * 12;

    unsigned long long acc[8][4];
    #pragma unroll
    for (int e = 0; e < 8; ++e)
        #pragma unroll
        for (int c = 0; c < 4; ++c) acc[e][c] = 0ull;

    const int tiles = (N + 7) >> 3;
    for (int tile = gw; tile < tiles; tile += nw) {
        const int base = tile * 8;

        #pragma unroll
        for (int r = 0; r < 4; ++r) {
            int nl = r * 2 + h;
            int ng = base + nl;
            if (ng < N) {
                #pragma unroll
                for (int q = 0; q < 3; ++q) {
                    int off = cg + q * 4;
                    float4 v;
                    if (off < D_IN)
                        v = *reinterpret_cast<const float4*>(nfeats + (size_t)ng * D_IN + off);
                    else
                        v = *reinterpret_cast<const float4*>(g_hneigh + (size_t)ng * D_OUT + (off - D_IN));
                    *reinterpret_cast<float4*>(xw + nl * 196 + off) = v;
                }
            }
        }
        __syncwarp();

        #pragma unroll 4
        for (int t = 0; t < 48; ++t) {
            const int wq = ((t ^ s7) << 2);
            ulonglong2 w0 = *reinterpret_cast<const ulonglong2*>(wl + wq);
            ulonglong2 w1 = *reinterpret_cast<const ulonglong2*>(wl + 192 + wq);
            ulonglong2 w2 = *reinterpret_cast<const ulonglong2*>(wl + 384 + wq);
            ulonglong2 w3 = *reinterpret_cast<const ulonglong2*>(wl + 576 + wq);
            #pragma unroll
            for (int e = 0; e < 8; ++e) {
                ulonglong2 xv = *reinterpret_cast<const ulonglong2*>(xw + e * 196 + t * 4);
                ffma2(acc[e][0], xv.x, w0.x); ffma2(acc[e][0], xv.y, w0.y);
                ffma2(acc[e][1], xv.x, w1.x); ffma2(acc[e][1], xv.y, w1.y);
                ffma2(acc[e][2], xv.x, w2.x); ffma2(acc[e][2], xv.y, w2.y);
                ffma2(acc[e][3], xv.x, w3.x); ffma2(acc[e][3], xv.y, w3.y);
            }
        }

        #pragma unroll
        for (int e = 0; e < 8; ++e) {
            int ng = base + e;
            float2 f0 = unpack2(acc[e][0]);
            float2 f1 = unpack2(acc[e][1]);
            float2 f2 = unpack2(acc[e][2]);
            float2 f3 = unpack2(acc[e][3]);
            float4 o;
            o.x = fmaxf(f0.x + f0.y + bias4.x, 0.f);
            o.y = fmaxf(f1.x + f1.y + bias4.y, 0.f);
            o.z = fmaxf(f2.x + f2.y + bias4.z, 0.f);
            o.w = fmaxf(f3.x + f3.y + bias4.w, 0.f);
            if (ng < N)
                *reinterpret_cast<float4*>(out + (size_t)ng * D_OUT + lane * 4) = o;
            acc[e][0] = 0ull; acc[e][1] = 0ull; acc[e][2] = 0ull; acc[e][3] = 0ull;
        }
        __syncwarp();
    }
}

extern "C" void kernel_launch(void* const* d_in, const int* in_sizes, int n_in,
                              void* d_out, int out_size)
{
    const float* nfeats = (const float*)d_in[0];
    const float* efeats = (const float*)d_in[1];
    const float* Wmsg   = (const float*)d_in[2];
    const float* bmsg   = (const float*)d_in[3];
    const float* Wap    = (const float*)d_in[4];
    const float* bap    = (const float*)d_in[5];
    const int*   src    = (const int*)d_in[6];
    const int*   dst    = (const int*)d_in[7];

    const int E = in_sizes[6];
    const int N = in_sizes[0] / D_IN;

    const size_t smem_edge  = SM_EDGE_BYTES;                    // 98816 B (2 CTAs/SM)
    const size_t smem_apply = A_SMEM_FLOATS * sizeof(float);    // 148992 B
    cudaFuncSetAttribute(edge_msg_kernel, cudaFuncAttributeMaxDynamicSharedMemorySize, (int)smem_edge);
    cudaFuncSetAttribute(apply_kernel,    cudaFuncAttributeMaxDynamicSharedMemorySize, (int)smem_apply);

    unsigned char* nconv_p; cudaGetSymbolAddress((void**)&nconv_p, g_nconv);
    unsigned char* econv_p; cudaGetSymbolAddress((void**)&econv_p, g_econv);

    // prepass conversions (fp16 hi/lo)
    {
        int nchunks = N * 16;
        conv_split_kernel<<<(nchunks + 255) / 256, 256>>>(
            (const float4*)nfeats, nconv_p, nchunks);
        int echunks = E * 16;
        conv_split_kernel<<<(echunks + 255) / 256, 256>>>(
            (const float4*)efeats, econv_p, echunks);
    }

    const int n4 = (N * D_OUT) / 4;
    zero_hneigh_kernel<<<(n4 + 255) / 256, 256>>>(n4);
    edge_msg_kernel<<<296, 256, smem_edge>>>(Wmsg, bmsg, src, dst, E);
    apply_kernel<<<152, 256, smem_apply>>>(nfeats, Wap, bap, (float*)d_out, N);
}